// round 5
// baseline (speedup 1.0000x reference)
#include <cuda_runtime.h>

// CREStereo fused bilinear-warp + 9-tap group correlation.
// left/right: [B,C,H,W] f32, flow: [B,2,H,W] f32
// out: [B, G*9, H, W] f32
// out[b, g*9+o, y, x] = mean_c( left[b,g*64+c,y,x] * warped[b,g*64+c,y,clamp(x+o-4)] )
// warped = bilinear(right, x+fx, y+fy), zero outside image.

#define BB     4
#define CC_T   256
#define HH     128
#define WW     256
#define GG     4
#define CG     64
#define WIN    9
#define CCH    4                 // channels per chunk
#define NCHUNK (CG / CCH)        // 16

__global__ __launch_bounds__(256, 2)
void crestereo_corr_kernel(const float* __restrict__ left,
                           const float* __restrict__ right,
                           const float* __restrict__ flow,
                           float* __restrict__ out)
{
    __shared__ __align__(16) float sh[2][CCH][WW];   // double-buffered warped chunk
    __shared__ float red[64 * 37];                   // padded reduction buffer

    // bid = ((b*H + y)*G + g): adjacent-y CTAs adjacent -> L2 reuse of right rows
    const int bid = blockIdx.x;
    const int g   = bid & (GG - 1);
    const int by  = bid >> 2;
    const int y   = by & (HH - 1);
    const int b   = by >> 7;

    const int tid = threadIdx.x;
    const int x   = tid;            // gather pixel
    const int pg  = tid & 63;       // corr pixel group: pixels 4pg..4pg+3
    const int s   = tid >> 6;       // corr channel-in-chunk (0..3)

    // ---- per-pixel bilinear params (once) ----
    const float fx = flow[((b * 2 + 0) * HH + y) * WW + x];
    const float fy = flow[((b * 2 + 1) * HH + y) * WW + x];
    const float sx = (float)x + fx;
    const float sy = (float)y + fy;
    const float x0f = floorf(sx);
    const float y0f = floorf(sy);
    const float axf = sx - x0f;
    const float ayf = sy - y0f;
    const int x0 = (int)x0f, y0 = (int)y0f;
    const int x1 = x0 + 1,   y1 = y0 + 1;

    float w00 = (1.f - axf) * (1.f - ayf);
    float w01 = axf * (1.f - ayf);
    float w10 = (1.f - axf) * ayf;
    float w11 = axf * ayf;

    const bool vx0 = ((unsigned)x0 < (unsigned)WW);
    const bool vx1 = ((unsigned)x1 < (unsigned)WW);
    const bool vy0 = ((unsigned)y0 < (unsigned)HH);
    const bool vy1 = ((unsigned)y1 < (unsigned)HH);
    if (!(vx0 && vy0)) w00 = 0.f;
    if (!(vx1 && vy0)) w01 = 0.f;
    if (!(vx0 && vy1)) w10 = 0.f;
    if (!(vx1 && vy1)) w11 = 0.f;

    const int cx0 = min(max(x0, 0), WW - 1);
    const int cx1 = min(max(x1, 0), WW - 1);
    const int cy0 = min(max(y0, 0), HH - 1);
    const int cy1 = min(max(y1, 0), HH - 1);

    // Paired column loads: aligned float2 at column e covers {e, e+1}.
    const int  e     = cx0 & ~1;
    const bool odd   = (cx0 & 1) != 0;
    const bool needS = (cx1 != e + 1);   // odd-normal or left-edge clamp cases
    const int ro0 = cy0 * WW + e;        // 8B-aligned (W even, e even)
    const int ro1 = cy1 * WW + e;
    const int so0 = cy0 * WW + cx1;
    const int so1 = cy1 * WW + cx1;

    const float* __restrict__ rbase = right + (size_t)(b * CC_T + g * CG) * (HH * WW);
    const float* __restrict__ lbase = left  + (size_t)(b * CC_T + g * CG + s) * (HH * WW)
                                            + (size_t)y * WW + 4 * pg;

    float acc[WIN][4];
#pragma unroll
    for (int o = 0; o < WIN; o++)
#pragma unroll
        for (int p = 0; p < 4; p++) acc[o][p] = 0.f;

    float2 f0[CCH], f1[CCH];
    float  p0[CCH], p1[CCH];

#define GATHER_RAW(CBASE)                                                       \
    {                                                                           \
        _Pragma("unroll")                                                       \
        for (int cc = 0; cc < CCH; cc++) {                                      \
            const float* __restrict__ rp = rbase + (size_t)((CBASE) + cc) * (HH * WW); \
            f0[cc] = *reinterpret_cast<const float2*>(rp + ro0);                \
            f1[cc] = *reinterpret_cast<const float2*>(rp + ro1);                \
            p0[cc] = 0.f; p1[cc] = 0.f;                                         \
            if (needS) { p0[cc] = __ldg(rp + so0); p1[cc] = __ldg(rp + so1); }  \
        }                                                                       \
    }

#define COMBINE_STS(BUF)                                                        \
    {                                                                           \
        _Pragma("unroll")                                                       \
        for (int cc = 0; cc < CCH; cc++) {                                      \
            float v0a = odd   ? f0[cc].y : f0[cc].x;                            \
            float v1a = needS ? p0[cc]   : f0[cc].y;                            \
            float v0b = odd   ? f1[cc].y : f1[cc].x;                            \
            float v1b = needS ? p1[cc]   : f1[cc].y;                            \
            sh[BUF][cc][x] = w00 * v0a + w01 * v1a + w10 * v0b + w11 * v1b;     \
        }                                                                       \
    }

    // prologue: chunk 0 -> buffer 0
    GATHER_RAW(0);
    COMBINE_STS(0);
    __syncthreads();

    const int wbase = 4 * pg - 4;
    const int abase = max(wbase, 0);
    const int cbase = min(4 * pg + 4, WW - 4);

    for (int i = 0; i < NCHUNK; i++) {
        const int cur = i & 1;

        if (i + 1 < NCHUNK) GATHER_RAW((i + 1) * CCH);   // prefetch (latency overlaps corr)

        // correlation: channel s of chunk i, pixels 4pg..4pg+3
        {
            const float* __restrict__ row = sh[cur][s];
            const float4 a  = *reinterpret_cast<const float4*>(row + abase);
            const float4 bq = *reinterpret_cast<const float4*>(row + 4 * pg);
            const float4 cq = *reinterpret_cast<const float4*>(row + cbase);
            float w_[12] = {a.x, a.y, a.z, a.w, bq.x, bq.y, bq.z, bq.w,
                            cq.x, cq.y, cq.z, cq.w};
            if (pg == 0)  { w_[0] = w_[1] = w_[2]  = w_[3]  = bq.x; }  // replicate col 0
            if (pg == 63) { w_[8] = w_[9] = w_[10] = w_[11] = cq.w; }  // replicate col 255

            const float4 l4 = *reinterpret_cast<const float4*>(lbase + (size_t)(i * CCH) * (HH * WW));
            const float lv[4] = {l4.x, l4.y, l4.z, l4.w};
#pragma unroll
            for (int o = 0; o < WIN; o++)
#pragma unroll
                for (int p = 0; p < 4; p++)
                    acc[o][p] = fmaf(lv[p], w_[p + o], acc[o][p]);
        }

        if (i + 1 < NCHUNK) COMBINE_STS((i + 1) & 1);    // other buffer: no hazard w/ corr reads
        __syncthreads();
    }

    // ---- 4-way reduction over channel subsets s=0..3 (main loop ended with sync) ----
    float* accf = &acc[0][0];
#pragma unroll
    for (int r = 1; r <= 3; r++) {
        if (s == r) {
#pragma unroll
            for (int j = 0; j < 36; j++) red[pg * 37 + j] = accf[j];
        }
        __syncthreads();
        if (s == 0) {
#pragma unroll
            for (int j = 0; j < 36; j++) accf[j] += red[pg * 37 + j];
        }
        __syncthreads();
    }

    if (s == 0) {
        const float scale = 1.f / (float)CG;
        float* __restrict__ ob = out + (((size_t)(b * GG + g) * WIN) * HH + y) * WW + 4 * pg;
#pragma unroll
        for (int o = 0; o < WIN; o++) {
            float4 v = make_float4(acc[o][0] * scale, acc[o][1] * scale,
                                   acc[o][2] * scale, acc[o][3] * scale);
            *reinterpret_cast<float4*>(ob + (size_t)o * HH * WW) = v;
        }
    }
}

extern "C" void kernel_launch(void* const* d_in, const int* in_sizes, int n_in,
                              void* d_out, int out_size)
{
    const float* left  = (const float*)d_in[0];
    const float* right = (const float*)d_in[1];
    const float* flow  = (const float*)d_in[2];
    float* out = (float*)d_out;

    const int grid = BB * HH * GG;   // 2048 CTAs
    crestereo_corr_kernel<<<grid, 256>>>(left, right, flow, out);
}

// round 6
// speedup vs baseline: 1.0506x; 1.0506x over previous
#include <cuda_runtime.h>

// CREStereo fused bilinear-warp + 9-tap group correlation.
// left/right: [B,C,H,W] f32, flow: [B,2,H,W] f32
// out: [B, G*9, H, W] f32
// out[b, g*9+o, y, x] = mean_c( left[b,g*64+c,y,x] * warped[b,g*64+c,y,clamp(x+o-4)] )
// warped = bilinear(right, x+fx, y+fy), zero outside image.

#define BB     4
#define CC_T   256
#define HH     128
#define WW     256
#define GG     4
#define CG     64
#define WIN    9
#define CCH    8
#define NCHUNK (CG / CCH)
#define HW     (HH * WW)

__global__ __launch_bounds__(256, 3)
void crestereo_corr_kernel(const float* __restrict__ left,
                           const float* __restrict__ right,
                           const float* __restrict__ flow,
                           float* __restrict__ out)
{
    // gather view: [CCH][WW] = 2048 floats; reduction view: [128][19] = 2432 floats
    __shared__ __align__(16) float sh[2432];

    // bid = ((b*H + y)*G + g): adjacent-y CTAs adjacent -> L2 reuse of right rows
    const int bid = blockIdx.x;
    const int g   = bid & (GG - 1);
    const int by  = bid >> 2;
    const int y   = by & (HH - 1);
    const int b   = by >> 7;

    const int tid = threadIdx.x;
    const int x   = tid;            // gather pixel
    const int pp  = tid & 127;      // corr pixel pair: pixels {2pp, 2pp+1}
    const int s   = tid >> 7;       // corr channel half (0/1) within chunk

    // ---- per-pixel bilinear params (gather role) ----
    const float fx = flow[((b * 2 + 0) * HH + y) * WW + x];
    const float fy = flow[((b * 2 + 1) * HH + y) * WW + x];
    const float sx = (float)x + fx;
    const float sy = (float)y + fy;
    const float x0f = floorf(sx);
    const float y0f = floorf(sy);
    const float axf = sx - x0f;
    const float ayf = sy - y0f;
    const int x0 = (int)x0f, y0 = (int)y0f;
    const int x1 = x0 + 1,   y1 = y0 + 1;

    float w00 = (1.f - axf) * (1.f - ayf);
    float w01 = axf * (1.f - ayf);
    float w10 = (1.f - axf) * ayf;
    float w11 = axf * ayf;

    const bool vx0 = ((unsigned)x0 < (unsigned)WW);
    const bool vx1 = ((unsigned)x1 < (unsigned)WW);
    const bool vy0 = ((unsigned)y0 < (unsigned)HH);
    const bool vy1 = ((unsigned)y1 < (unsigned)HH);
    if (!(vx0 && vy0)) w00 = 0.f;
    if (!(vx1 && vy0)) w01 = 0.f;
    if (!(vx0 && vy1)) w10 = 0.f;
    if (!(vx1 && vy1)) w11 = 0.f;

    const int cx0 = min(max(x0, 0), WW - 1);
    const int cx1 = min(max(x1, 0), WW - 1);
    const int cy0 = min(max(y0, 0), HH - 1);
    const int cy1 = min(max(y1, 0), HH - 1);

    // Paired column loads: aligned float2 at even column e covers {e, e+1}.
    const int  e     = cx0 & ~1;
    const bool odd   = (cx0 & 1) != 0;
    const bool needS = (cx1 != e + 1);    // odd-normal or left-edge clamp
    const int ro0 = cy0 * WW + e;         // 8B-aligned
    const int ro1 = cy1 * WW + e;
    const int so0 = cy0 * WW + cx1;
    const int so1 = cy1 * WW + cx1;

    const float* __restrict__ rbase = right + (size_t)(b * CC_T + g * CG) * HW;
    const float* __restrict__ lbase = left  + (size_t)(b * CC_T + g * CG + s * 4) * HW
                                            + (size_t)y * WW + 2 * pp;

    // ---- corr precompute: 5 aligned float2 bases covering [2pp-4, 2pp+6) ----
    int bofs[5];
#pragma unroll
    for (int j = 0; j < 5; j++) bofs[j] = min(max(2 * pp - 4 + 2 * j, 0), WW - 2);
    const bool e0   = (pp == 0);
    const bool e1   = (pp == 1);
    const bool e126 = (pp == 126);
    const bool e127 = (pp == 127);

    float acc[WIN][2];
#pragma unroll
    for (int o = 0; o < WIN; o++) { acc[o][0] = 0.f; acc[o][1] = 0.f; }

    for (int i = 0; i < NCHUNK; i++) {
        __syncthreads();   // previous chunk's corr reads complete before overwrite
        // ---- gather: warp pixel x for 8 channels ----
#pragma unroll
        for (int cc = 0; cc < CCH; cc++) {
            const float* __restrict__ rp = rbase + (size_t)(i * CCH + cc) * HW;
            const float2 a0 = *reinterpret_cast<const float2*>(rp + ro0);
            const float2 a1 = *reinterpret_cast<const float2*>(rp + ro1);
            float q0 = 0.f, q1 = 0.f;
            if (needS) { q0 = __ldg(rp + so0); q1 = __ldg(rp + so1); }
            const float v0a = odd   ? a0.y : a0.x;
            const float v1a = needS ? q0   : a0.y;
            const float v0b = odd   ? a1.y : a1.x;
            const float v1b = needS ? q1   : a1.y;
            sh[cc * WW + x] = w00 * v0a + w01 * v1a + w10 * v0b + w11 * v1b;
        }
        __syncthreads();
        // ---- corr: 4 channels (half-chunk s), pixels {2pp, 2pp+1} ----
#pragma unroll
        for (int cc = 0; cc < 4; cc++) {
            const float* __restrict__ row = sh + (s * 4 + cc) * WW;
            const float2 l2 = *reinterpret_cast<const float2*>(
                                  lbase + (size_t)(i * CCH + cc) * HW);
            const float2 f0_ = *reinterpret_cast<const float2*>(row + bofs[0]);
            const float2 f1_ = *reinterpret_cast<const float2*>(row + bofs[1]);
            const float2 f2_ = *reinterpret_cast<const float2*>(row + bofs[2]);
            const float2 f3_ = *reinterpret_cast<const float2*>(row + bofs[3]);
            const float2 f4_ = *reinterpret_cast<const float2*>(row + bofs[4]);
            float w_[10] = {f0_.x, f0_.y, f1_.x, f1_.y, f2_.x,
                            f2_.y, f3_.x, f3_.y, f4_.x, f4_.y};
            // replicate-pad fixups (static per thread)
            if (e0)   { w_[1] = f0_.x; w_[3] = f0_.x; }
            if (e1)   { w_[1] = f0_.x; }
            if (e127) { w_[6] = f3_.y; w_[8] = f4_.y; }
            if (e126) { w_[8] = f4_.y; }
#pragma unroll
            for (int o = 0; o < WIN; o++) {
                acc[o][0] = fmaf(l2.x, w_[o],     acc[o][0]);
                acc[o][1] = fmaf(l2.y, w_[o + 1], acc[o][1]);
            }
        }
    }

    // ---- 2-way reduction over channel halves, then store ----
    __syncthreads();
    if (s == 1) {
#pragma unroll
        for (int o = 0; o < WIN; o++) {
            sh[pp * 19 + 2 * o]     = acc[o][0];
            sh[pp * 19 + 2 * o + 1] = acc[o][1];
        }
    }
    __syncthreads();
    if (s == 0) {
        const float scale = 1.f / (float)CG;
        float* __restrict__ ob = out + (((size_t)(b * GG + g) * WIN) * HH + y) * WW + 2 * pp;
#pragma unroll
        for (int o = 0; o < WIN; o++) {
            float2 v;
            v.x = (acc[o][0] + sh[pp * 19 + 2 * o])     * scale;
            v.y = (acc[o][1] + sh[pp * 19 + 2 * o + 1]) * scale;
            *reinterpret_cast<float2*>(ob + (size_t)o * HW) = v;
        }
    }
}

extern "C" void kernel_launch(void* const* d_in, const int* in_sizes, int n_in,
                              void* d_out, int out_size)
{
    const float* left  = (const float*)d_in[0];
    const float* right = (const float*)d_in[1];
    const float* flow  = (const float*)d_in[2];
    float* out = (float*)d_out;

    const int grid = BB * HH * GG;   // 2048 CTAs
    crestereo_corr_kernel<<<grid, 256>>>(left, right, flow, out);
}